// round 16
// baseline (speedup 1.0000x reference)
#include <cuda_runtime.h>
#include <math.h>
#include <stdint.h>

#define NMAX 100000
#define EMAX 600000
#define IN_F 128
#define OUT_F 64

// Scratch (static device globals — allocation-free per harness rules)
__device__ float  g_Wsn[IN_F * OUT_F];
__device__ float  g_xp[(size_t)NMAX * OUT_F];
__device__ float  g_deg[NMAX];
__device__ float  g_w[EMAX];
__device__ int2   g_rc[EMAX];
__device__ int    g_cnt[NMAX];
__device__ int    g_ofs[NMAX];
__device__ int    g_cursor[NMAX];
__device__ float2 g_csr[EMAX];
__device__ int    g_alloc;
__device__ int    g_is64;

__device__ __forceinline__ long long load_idx(const void* ei, size_t pos, int is64) {
    if (is64) return ((const long long*)ei)[pos];
    return (long long)(((const int*)ei)[pos]);
}

// ---------------------------------------------------------------------------
// 1) k_prep: b0 detect + reset alloc | b1 spectral -> g_Wsn | rest: deg=1, cnt=0
// ---------------------------------------------------------------------------
__global__ void k_prep(const unsigned int* __restrict__ ei_u32, int nwords,
                       const float* __restrict__ W, const float* __restrict__ u,
                       int N) {
    int t = threadIdx.x;
    int b = blockIdx.x;

    if (b == 0) {
        __shared__ int any;
        if (t == 0) { any = 0; g_alloc = 0; }
        __syncthreads();
        int limit = nwords < 8192 ? nwords : 8192;
        for (int i = 1 + 2 * t; i < limit; i += 2 * blockDim.x)
            if (ei_u32[i] != 0u) any = 1;
        __syncthreads();
        if (t == 0) g_is64 = (any == 0) ? 1 : 0;
        return;
    }
    if (b == 1) {
        __shared__ float su[IN_F];
        __shared__ float sv[OUT_F];
        __shared__ float red1[4][OUT_F];
        __shared__ float red16[16];
        __shared__ float rsum[8];
        __shared__ float s_tn, s_inv;

        if (t < IN_F) su[t] = u[t];
        __syncthreads();

        {
            int j = t & 63;
            int q = t >> 6;
            float p = 0.f;
            int i0 = q * 32;
            #pragma unroll 8
            for (int i = 0; i < 32; i++) p += W[(i0 + i) * OUT_F + j] * su[i0 + i];
            red1[q][j] = p;
        }
        __syncthreads();

        float tj = 0.f;
        if (t < OUT_F) {
            tj = red1[0][t] + red1[1][t] + red1[2][t] + red1[3][t];
            float sq = tj * tj;
            #pragma unroll
            for (int o = 16; o > 0; o >>= 1) sq += __shfl_down_sync(0xffffffffu, sq, o);
            if ((t & 31) == 0) rsum[t >> 5] = sq;
        }
        __syncthreads();
        if (t == 0) s_tn = sqrtf(rsum[0] + rsum[1]) + 1e-12f;
        __syncthreads();
        if (t < OUT_F) sv[t] = tj / s_tn;
        __syncthreads();

        {
            int hw = t >> 4;
            int k = t & 15;
            float sq = 0.f;
            #pragma unroll
            for (int p = 0; p < 8; p++) {
                int r = p * 16 + hw;
                const float* wr = &W[r * OUT_F];
                float partial = wr[k]      * sv[k]
                              + wr[k + 16] * sv[k + 16]
                              + wr[k + 32] * sv[k + 32]
                              + wr[k + 48] * sv[k + 48];
                #pragma unroll
                for (int o = 8; o > 0; o >>= 1)
                    partial += __shfl_down_sync(0xffffffffu, partial, o, 16);
                if (k == 0) sq += partial * partial;
            }
            if (k == 0) red16[hw] = sq;
        }
        __syncthreads();
        if (t == 0) {
            float s2 = 0.f;
            #pragma unroll
            for (int i = 0; i < 16; i++) s2 += red16[i];
            float sigma = s2 / (sqrtf(s2) + 1e-12f);
            s_inv = 1.0f / sigma;
        }
        __syncthreads();

        {
            float inv = s_inv;
            const float4* W4 = reinterpret_cast<const float4*>(W);
            float4* O4 = reinterpret_cast<float4*>(g_Wsn);
            #pragma unroll
            for (int i = 0; i < 8; i++) {
                int idx = t + i * 256;
                float4 v = W4[idx];
                O4[idx] = make_float4(v.x * inv, v.y * inv, v.z * inv, v.w * inv);
            }
        }
        return;
    }
    int i = (b - 2) * blockDim.x + t;
    if (i < N) { g_deg[i] = 1.0f; g_cnt[i] = 0; }
}

// ---------------------------------------------------------------------------
// 2) k_fused: deg blocks (sigmoid, deg+=w, cnt++, pack rc) overlap GEMM blocks
// ---------------------------------------------------------------------------
#define BK 32
#define XS_STRIDE 132
#define WS_STRIDE 17

__global__ void __launch_bounds__(256) k_fused(const float* __restrict__ x,
                                               const void* __restrict__ ei,
                                               const float* __restrict__ ew,
                                               int N, int E, int nbDeg) {
    int t = threadIdx.x;
    int b = blockIdx.x;

    if (b < nbDeg) {
        int e = (b * blockDim.x + t) * 4;
        if (e >= E) return;
        int is64 = g_is64;
        if (e + 3 < E) {
            float4 w4 = *reinterpret_cast<const float4*>(ew + e);
            float4 s;
            s.x = 1.0f / (1.0f + expf(-w4.x));
            s.y = 1.0f / (1.0f + expf(-w4.y));
            s.z = 1.0f / (1.0f + expf(-w4.z));
            s.w = 1.0f / (1.0f + expf(-w4.w));
            *reinterpret_cast<float4*>(g_w + e) = s;
            int r0, r1, r2, r3, c0, c1, c2, c3;
            if (is64) {
                const longlong2* pr = reinterpret_cast<const longlong2*>((const long long*)ei + e);
                longlong2 a = pr[0], bq = pr[1];
                r0 = (int)a.x; r1 = (int)a.y; r2 = (int)bq.x; r3 = (int)bq.y;
                const longlong2* pc = reinterpret_cast<const longlong2*>((const long long*)ei + E + e);
                longlong2 d = pc[0], f = pc[1];
                c0 = (int)d.x; c1 = (int)d.y; c2 = (int)f.x; c3 = (int)f.y;
            } else {
                int4 rr = *reinterpret_cast<const int4*>((const int*)ei + e);
                r0 = rr.x; r1 = rr.y; r2 = rr.z; r3 = rr.w;
                int4 cc = *reinterpret_cast<const int4*>((const int*)ei + E + e);
                c0 = cc.x; c1 = cc.y; c2 = cc.z; c3 = cc.w;
            }
            int4* rcp = reinterpret_cast<int4*>(&g_rc[e]);
            rcp[0] = make_int4(r0, c0, r1, c1);
            rcp[1] = make_int4(r2, c2, r3, c3);
            atomicAdd(&g_deg[c0], s.x);
            atomicAdd(&g_deg[c1], s.y);
            atomicAdd(&g_deg[c2], s.z);
            atomicAdd(&g_deg[c3], s.w);
            atomicAdd(&g_cnt[c0], 1);
            atomicAdd(&g_cnt[c1], 1);
            atomicAdd(&g_cnt[c2], 1);
            atomicAdd(&g_cnt[c3], 1);
        } else {
            for (int k = e; k < E; k++) {
                float w = 1.0f / (1.0f + expf(-ew[k]));
                g_w[k] = w;
                int r = (int)load_idx(ei, (size_t)k, is64);
                int c = (int)load_idx(ei, (size_t)E + k, is64);
                g_rc[k] = make_int2(r, c);
                atomicAdd(&g_deg[c], w);
                atomicAdd(&g_cnt[c], 1);
            }
        }
        return;
    }

    // ---- gemm path ----
    __shared__ float  xs[BK * XS_STRIDE];
    __shared__ float4 ws[BK * WS_STRIDE];

    int gb = b - nbDeg;
    int tx = t & 15;
    int ty = t >> 4;
    int row0 = gb * 128;

    float4 acc[8];
    #pragma unroll
    for (int r = 0; r < 8; r++) acc[r] = make_float4(0.f, 0.f, 0.f, 0.f);

    const float4* Wg = reinterpret_cast<const float4*>(g_Wsn);

    for (int kc = 0; kc < IN_F; kc += BK) {
        #pragma unroll
        for (int i = 0; i < 2; i++) {
            int idx = t + i * 256;
            int kk = idx >> 4;
            int c4 = idx & 15;
            ws[kk * WS_STRIDE + c4] = Wg[(kc + kk) * 16 + c4];
        }
        #pragma unroll
        for (int i = 0; i < 4; i++) {
            int idx = t + i * 256;
            int r = idx >> 3;
            int k4 = (idx & 7) << 2;
            float4 v = make_float4(0.f, 0.f, 0.f, 0.f);
            if (row0 + r < N)
                v = *reinterpret_cast<const float4*>(&x[(size_t)(row0 + r) * IN_F + kc + k4]);
            xs[(k4 + 0) * XS_STRIDE + r] = v.x;
            xs[(k4 + 1) * XS_STRIDE + r] = v.y;
            xs[(k4 + 2) * XS_STRIDE + r] = v.z;
            xs[(k4 + 3) * XS_STRIDE + r] = v.w;
        }
        __syncthreads();

        #pragma unroll 8
        for (int kk = 0; kk < BK; kk++) {
            float4 a0 = *reinterpret_cast<const float4*>(&xs[kk * XS_STRIDE + ty * 8]);
            float4 a1 = *reinterpret_cast<const float4*>(&xs[kk * XS_STRIDE + ty * 8 + 4]);
            float4 bb = ws[kk * WS_STRIDE + tx];
            acc[0].x += a0.x * bb.x; acc[0].y += a0.x * bb.y; acc[0].z += a0.x * bb.z; acc[0].w += a0.x * bb.w;
            acc[1].x += a0.y * bb.x; acc[1].y += a0.y * bb.y; acc[1].z += a0.y * bb.z; acc[1].w += a0.y * bb.w;
            acc[2].x += a0.z * bb.x; acc[2].y += a0.z * bb.y; acc[2].z += a0.z * bb.z; acc[2].w += a0.z * bb.w;
            acc[3].x += a0.w * bb.x; acc[3].y += a0.w * bb.y; acc[3].z += a0.w * bb.z; acc[3].w += a0.w * bb.w;
            acc[4].x += a1.x * bb.x; acc[4].y += a1.x * bb.y; acc[4].z += a1.x * bb.z; acc[4].w += a1.x * bb.w;
            acc[5].x += a1.y * bb.x; acc[5].y += a1.y * bb.y; acc[5].z += a1.y * bb.z; acc[5].w += a1.y * bb.w;
            acc[6].x += a1.z * bb.x; acc[6].y += a1.z * bb.y; acc[6].z += a1.z * bb.z; acc[6].w += a1.z * bb.w;
            acc[7].x += a1.w * bb.x; acc[7].y += a1.w * bb.y; acc[7].z += a1.w * bb.z; acc[7].w += a1.w * bb.w;
        }
        __syncthreads();
    }

    #pragma unroll
    for (int r = 0; r < 8; r++) {
        int row = row0 + ty * 8 + r;
        if (row >= N) break;
        *reinterpret_cast<float4*>(&g_xp[(size_t)row * OUT_F + tx * 4]) = acc[r];
    }
}

// ---------------------------------------------------------------------------
// 3) k_alloc: contiguous per-node CSR ranges via warp-aggregated bump alloc.
//    (Range order across nodes is arbitrary — addition commutes.)
// ---------------------------------------------------------------------------
__global__ void k_alloc(int N) {
    int i = blockIdx.x * blockDim.x + threadIdx.x;
    int lane = threadIdx.x & 31;
    int cnt = (i < N) ? g_cnt[i] : 0;

    // inclusive warp scan
    int incl = cnt;
    #pragma unroll
    for (int o = 1; o < 32; o <<= 1) {
        int v = __shfl_up_sync(0xffffffffu, incl, o);
        if (lane >= o) incl += v;
    }
    int total = __shfl_sync(0xffffffffu, incl, 31);
    int base = 0;
    if (lane == 31) base = atomicAdd(&g_alloc, total);
    base = __shfl_sync(0xffffffffu, base, 31);
    int ofs = base + incl - cnt;   // exclusive
    if (i < N) { g_ofs[i] = ofs; g_cursor[i] = ofs; }
}

// ---------------------------------------------------------------------------
// 4) k_fill: place (src, ne) into destination's CSR range.
// ---------------------------------------------------------------------------
__global__ void k_fill(int E) {
    int e = blockIdx.x * blockDim.x + threadIdx.x;
    if (e >= E) return;
    int2 rc = g_rc[e];
    float ne = g_w[e] * rsqrtf(g_deg[rc.x]) * rsqrtf(g_deg[rc.y]);
    int pos = atomicAdd(&g_cursor[rc.y], 1);
    g_csr[pos] = make_float2(__int_as_float(rc.x), ne);
}

// ---------------------------------------------------------------------------
// 5) k_gather: 16 lanes/node. acc = sum_in xp[src]*ne; out = acc + xp/deg + bias.
//    Pure loads + one plain float4 store — zero output atomics.
// ---------------------------------------------------------------------------
__global__ void k_gather(const float* __restrict__ bias, float* __restrict__ out, int N) {
    int gid = blockIdx.x * blockDim.x + threadIdx.x;
    int node = gid >> 4;
    if (node >= N) return;
    int lane = gid & 15;

    int ofs = g_ofs[node];          // broadcast
    int end = g_cursor[node];       // = ofs + cnt after fill

    float4 acc = make_float4(0.f, 0.f, 0.f, 0.f);
    for (int j = ofs; j < end; j++) {
        float2 pr = g_csr[j];       // broadcast (16 lanes same addr)
        int r = __float_as_int(pr.x);
        float ne = pr.y;
        float4 v = *reinterpret_cast<const float4*>(&g_xp[(size_t)r * OUT_F + lane * 4]);
        acc.x = fmaf(v.x, ne, acc.x);
        acc.y = fmaf(v.y, ne, acc.y);
        acc.z = fmaf(v.z, ne, acc.z);
        acc.w = fmaf(v.w, ne, acc.w);
    }

    float invd = 1.0f / g_deg[node];
    float4 s = *reinterpret_cast<const float4*>(&g_xp[(size_t)node * OUT_F + lane * 4]);
    float4 bb = reinterpret_cast<const float4*>(bias)[lane];
    *reinterpret_cast<float4*>(&out[(size_t)node * OUT_F + lane * 4]) =
        make_float4(fmaf(s.x, invd, acc.x + bb.x), fmaf(s.y, invd, acc.y + bb.y),
                    fmaf(s.z, invd, acc.z + bb.z), fmaf(s.w, invd, acc.w + bb.w));
}

// ---------------------------------------------------------------------------
// Launch (5 launches, stream-ordered)
// ---------------------------------------------------------------------------
extern "C" void kernel_launch(void* const* d_in, const int* in_sizes, int n_in,
                              void* d_out, int out_size) {
    const float* x    = (const float*)d_in[0];
    const void*  ei   = d_in[1];
    const float* W    = (const float*)d_in[2];
    const float* bias = (const float*)d_in[3];
    const float* ew   = (const float*)d_in[4];
    const float* u    = (const float*)d_in[5];
    float*       out  = (float*)d_out;

    int N = in_sizes[0] / IN_F;
    int E = in_sizes[4];
    if (N > NMAX) N = NMAX;
    if (E > EMAX) E = EMAX;

    int nbInit = (N + 255) / 256;
    k_prep<<<2 + nbInit, 256>>>((const unsigned int*)ei, 2 * E, W, u, N);

    int nbDeg  = ((E + 3) / 4 + 255) / 256;
    int nbGemm = (N + 127) / 128;
    k_fused<<<nbDeg + nbGemm, 256>>>(x, ei, ew, N, E, nbDeg);

    k_alloc<<<(N + 255) / 256, 256>>>(N);
    k_fill<<<(E + 255) / 256, 256>>>(E);
    k_gather<<<(N * 16 + 255) / 256, 256>>>(bias, out, N);
}